// round 2
// baseline (speedup 1.0000x reference)
#include <cuda_runtime.h>
#include <math.h>

#define S_LEN   2048
#define BATCH   64
#define ISZ     512
#define HSZ     512
#define G3      1536
#define NLAYERS 2

// ---------------- device scratch (no cudaMalloc allowed) ----------------
__device__ float g_xlin[(size_t)S_LEN * BATCH * G3];   // 805 MB: per-layer input projections
__device__ float g_y1[(size_t)S_LEN * BATCH * HSZ];    // 256 MB: layer-0 outputs
__device__ float g_hbuf[2][BATCH * HSZ];               // ping-pong hidden state
__device__ unsigned int g_bar;                         // grid barrier counter

// =====================================================================
// GEMM: C[M,N] = A[M,K=512] * W[N,K=512]^T + bias[N]
// M = S*B = 131072, N = 1536. Classic 128x128x8 tile, 8x8 per thread.
// =====================================================================
#define BM 128
#define BN 128
#define BK 8
#define TM 8
#define TN 8

__global__ __launch_bounds__(256) void gemm_xproj(
    const float* __restrict__ A, const float* __restrict__ W,
    const float* __restrict__ bias, float* __restrict__ C)
{
    __shared__ float As[BK][BM];
    __shared__ float Bs[BK][BN];

    const int bx = blockIdx.x;   // N tile (0..11)
    const int by = blockIdx.y;   // M tile (0..1023)
    const int tid = threadIdx.x;
    const int tx = tid & 15;
    const int ty = tid >> 4;

    const float* Ab = A + (size_t)by * BM * ISZ;
    const float* Wb = W + (size_t)bx * BN * ISZ;

    const int lrow = tid >> 1;        // 0..127
    const int lcol = (tid & 1) * 4;   // 0 or 4

    float acc[TM][TN];
#pragma unroll
    for (int i = 0; i < TM; i++)
#pragma unroll
        for (int j = 0; j < TN; j++) acc[i][j] = 0.f;

    for (int k0 = 0; k0 < ISZ; k0 += BK) {
        float4 av = *(const float4*)(Ab + (size_t)lrow * ISZ + k0 + lcol);
        float4 wv = *(const float4*)(Wb + (size_t)lrow * ISZ + k0 + lcol);
        As[lcol + 0][lrow] = av.x; As[lcol + 1][lrow] = av.y;
        As[lcol + 2][lrow] = av.z; As[lcol + 3][lrow] = av.w;
        Bs[lcol + 0][lrow] = wv.x; Bs[lcol + 1][lrow] = wv.y;
        Bs[lcol + 2][lrow] = wv.z; Bs[lcol + 3][lrow] = wv.w;
        __syncthreads();

#pragma unroll
        for (int k = 0; k < BK; k++) {
            float4 a0 = *(const float4*)&As[k][ty * TM];
            float4 a1 = *(const float4*)&As[k][ty * TM + 4];
            float4 b0 = *(const float4*)&Bs[k][tx * TN];
            float4 b1 = *(const float4*)&Bs[k][tx * TN + 4];
            float af[TM] = {a0.x, a0.y, a0.z, a0.w, a1.x, a1.y, a1.z, a1.w};
            float bf[TN] = {b0.x, b0.y, b0.z, b0.w, b1.x, b1.y, b1.z, b1.w};
#pragma unroll
            for (int i = 0; i < TM; i++)
#pragma unroll
                for (int j = 0; j < TN; j++) acc[i][j] += af[i] * bf[j];
        }
        __syncthreads();
    }

    // epilogue: add bias, store
#pragma unroll
    for (int i = 0; i < TM; i++) {
        const size_t m = (size_t)by * BM + ty * TM + i;
#pragma unroll
        for (int j = 0; j < TN; j += 4) {
            const int n = bx * BN + tx * TN + j;
            float4 v;
            v.x = acc[i][j + 0] + __ldg(&bias[n + 0]);
            v.y = acc[i][j + 1] + __ldg(&bias[n + 1]);
            v.z = acc[i][j + 2] + __ldg(&bias[n + 2]);
            v.w = acc[i][j + 3] + __ldg(&bias[n + 3]);
            *(float4*)(C + m * G3 + n) = v;
        }
    }
}

// =====================================================================
// Recurrent GRU kernel: persistent, 128 blocks (32 h-chunks x 4 b-chunks),
// W_hh register-resident, one grid barrier per timestep (ping-pong h).
// =====================================================================
#define HC   16      // h indices per block
#define BC   16      // batches per block
#define NBLK ((HSZ / HC) * (BATCH / BC))   // 128
#define KSL  32      // K slice per thread
#define NKS  (HSZ / KSL)                   // 16 k-slices
#define REDS 9       // padded warp-partial stride (conflict-free: gcd(27,32)=1)

// smem layout (floats)
#define SM_HS   0                     // h_s[BC][HSZ]         = 8192
#define SM_RED  (BC * HSZ)            // red[256][3][REDS]    = 6912
#define SM_XL   (SM_RED + 256 * 3 * REDS)   // xl_s[3][256]   = 768
#define SM_BH   (SM_XL + 768)         // bh_s[3][HC]          = 48
#define SM_TOT  (SM_BH + 48)
#define SMEM_BYTES (SM_TOT * 4)

__device__ __forceinline__ void grid_bar(unsigned* epoch)
{
    __syncthreads();
    if (threadIdx.x == 0) {
        __threadfence();
        atomicAdd(&g_bar, 1u);
        const unsigned target = (++(*epoch)) * gridDim.x;
        volatile unsigned* p = &g_bar;
        while (*p < target) { }
        __threadfence();
    }
    __syncthreads();
}

__global__ __launch_bounds__(256, 1) void gru_recurrent(
    const float* __restrict__ xlin,   // [S*B][G3]  (b_ih already added)
    const float* __restrict__ whh,    // [G3][HSZ]  this layer
    const float* __restrict__ bhh,    // [G3]       this layer
    const float* __restrict__ hx,     // [B*HSZ]    initial hidden
    float* __restrict__ yout,         // [S*B*HSZ]  layer outputs
    float* __restrict__ hfin)         // [B*HSZ]    final hidden
{
    extern __shared__ float sm[];
    float* h_s  = sm + SM_HS;
    float* red  = sm + SM_RED;
    float* xl_s = sm + SM_XL;
    float* bh_s = sm + SM_BH;

    const int blk = blockIdx.x;
    const int hc = blk >> 2;          // 0..31
    const int bc = blk & 3;           // 0..3
    const int hbase = hc * HC;
    const int bbase = bc * BC;
    const int tid  = threadIdx.x;
    const int j    = tid & 15;        // h index within chunk (for matmul role)
    const int ks   = tid >> 4;        // k-slice 0..15
    const int lane = tid & 31;
    const int warp = tid >> 5;

    // ---- W_hh slice into registers: 3 gates x 32 k each ----
    float wr[KSL], wz[KSL], wn[KSL];
    {
        const float* rowr = whh + (size_t)(0 * HSZ + hbase + j) * HSZ + ks * KSL;
        const float* rowz = whh + (size_t)(1 * HSZ + hbase + j) * HSZ + ks * KSL;
        const float* rown = whh + (size_t)(2 * HSZ + hbase + j) * HSZ + ks * KSL;
#pragma unroll
        for (int k = 0; k < KSL; k++) {
            wr[k] = rowr[k]; wz[k] = rowz[k]; wn[k] = rown[k];
        }
    }
    if (tid < HC) {
        bh_s[tid]          = bhh[0 * HSZ + hbase + tid];
        bh_s[HC + tid]     = bhh[1 * HSZ + hbase + tid];
        bh_s[2 * HC + tid] = bhh[2 * HSZ + hbase + tid];
    }

    // ---- init hidden state (buffer 0) for this block's tile ----
    {
        const int jj = tid >> 4, bb = tid & 15;
        const size_t idx = (size_t)(bbase + bb) * HSZ + hbase + jj;
        g_hbuf[0][idx] = hx[idx];
    }
    unsigned epoch = 0;
    grid_bar(&epoch);

    for (int t = 0; t < S_LEN; t++) {
        // ---- stage h (our 16 batches, full H) and this step's xlin ----
        {
            const float4* src = (const float4*)(g_hbuf[t & 1] + (size_t)bbase * HSZ);
            float4* dst = (float4*)h_s;
#pragma unroll
            for (int r = 0; r < 8; r++)
                dst[tid + 256 * r] = __ldcg(src + tid + 256 * r);

            const int bb = tid >> 4, jj = tid & 15;
            const float* xp = xlin + ((size_t)t * BATCH + bbase + bb) * G3 + hbase + jj;
#pragma unroll
            for (int g = 0; g < 3; g++)
                xl_s[g * 256 + tid] = __ldg(xp + g * HSZ);
        }
        __syncthreads();

        // ---- matmul partials: thread (j, ks) does 3 gates over its k-slice ----
#pragma unroll 2
        for (int b = 0; b < BC; b++) {
            float ar = 0.f, az = 0.f, an = 0.f;
            const float4* hp = (const float4*)(h_s + b * HSZ + ks * KSL);
#pragma unroll
            for (int q = 0; q < KSL / 4; q++) {
                float4 hv = hp[q];
                ar += wr[4*q+0]*hv.x; az += wz[4*q+0]*hv.x; an += wn[4*q+0]*hv.x;
                ar += wr[4*q+1]*hv.y; az += wz[4*q+1]*hv.y; an += wn[4*q+1]*hv.y;
                ar += wr[4*q+2]*hv.z; az += wz[4*q+2]*hv.z; an += wn[4*q+2]*hv.z;
                ar += wr[4*q+3]*hv.w; az += wz[4*q+3]*hv.w; an += wn[4*q+3]*hv.w;
            }
            // fold k-slice pairs within the warp (ks and ks^1 live in same warp)
            ar += __shfl_xor_sync(0xffffffffu, ar, 16);
            az += __shfl_xor_sync(0xffffffffu, az, 16);
            an += __shfl_xor_sync(0xffffffffu, an, 16);
            if (lane < 16) {
                float* rb = red + ((b * HC + j) * 3) * REDS + warp;
                rb[0]        = ar;
                rb[REDS]     = az;
                rb[2 * REDS] = an;
            }
        }
        __syncthreads();

        // ---- reduce 8 warp-partials, apply gates, update h ----
        {
            const int jj = tid & 15;   // h index (contiguous stores)
            const int bb = tid >> 4;   // batch
            const float* rb = red + ((bb * HC + jj) * 3) * REDS;
            float hr = 0.f, hz = 0.f, hn = 0.f;
#pragma unroll
            for (int w = 0; w < 8; w++) {
                hr += rb[w]; hz += rb[REDS + w]; hn += rb[2 * REDS + w];
            }
            hr += bh_s[jj]; hz += bh_s[HC + jj]; hn += bh_s[2 * HC + jj];

            const float xr = xl_s[0 * 256 + tid];
            const float xz = xl_s[1 * 256 + tid];
            const float xn = xl_s[2 * 256 + tid];

            const float r = 1.f / (1.f + __expf(-(xr + hr)));
            const float z = 1.f / (1.f + __expf(-(xz + hz)));
            const float n = tanhf(xn + r * hn);

            const int bg = bbase + bb;
            const int hg = hbase + jj;
            const float hold = h_s[bb * HSZ + hg];
            const float hnew = (1.f - z) * n + z * hold;

            g_hbuf[(t + 1) & 1][(size_t)bg * HSZ + hg] = hnew;
            yout[((size_t)t * BATCH + bg) * HSZ + hg] = hnew;
            if (t == S_LEN - 1) hfin[(size_t)bg * HSZ + hg] = hnew;
        }
        grid_bar(&epoch);
    }
}

// =====================================================================
// kernel_launch
// =====================================================================
extern "C" void kernel_launch(void* const* d_in, const int* in_sizes, int n_in,
                              void* d_out, int out_size)
{
    (void)in_sizes; (void)n_in; (void)out_size;
    const float* x   = (const float*)d_in[0];
    const float* hx  = (const float*)d_in[1];
    const float* wih = (const float*)d_in[2];
    const float* whh = (const float*)d_in[3];
    const float* bih = (const float*)d_in[4];
    const float* bhh = (const float*)d_in[5];

    float* out    = (float*)d_out;                            // [S,B,H]
    float* hidden = out + (size_t)S_LEN * BATCH * HSZ;        // [L,B,H]

    float* xlin = nullptr; float* y1 = nullptr; unsigned* bar = nullptr;
    cudaGetSymbolAddress((void**)&xlin, g_xlin);
    cudaGetSymbolAddress((void**)&y1,   g_y1);
    cudaGetSymbolAddress((void**)&bar,  g_bar);

    cudaFuncSetAttribute(gru_recurrent,
                         cudaFuncAttributeMaxDynamicSharedMemorySize, SMEM_BYTES);

    const dim3 gemm_grid(G3 / BN, (S_LEN * BATCH) / BM);

    // ---- layer 0 ----
    gemm_xproj<<<gemm_grid, 256>>>(x, wih, bih, xlin);
    cudaMemsetAsync(bar, 0, sizeof(unsigned));
    gru_recurrent<<<NBLK, 256, SMEM_BYTES>>>(xlin, whh, bhh, hx, y1, hidden);

    // ---- layer 1 ----
    gemm_xproj<<<gemm_grid, 256>>>(y1, wih + (size_t)G3 * ISZ, bih + G3, xlin);
    cudaMemsetAsync(bar, 0, sizeof(unsigned));
    gru_recurrent<<<NBLK, 256, SMEM_BYTES>>>(xlin, whh + (size_t)G3 * HSZ, bhh + G3,
                                             hx + (size_t)BATCH * HSZ,
                                             out, hidden + (size_t)BATCH * HSZ);
}

// round 3
// speedup vs baseline: 1.0378x; 1.0378x over previous
#include <cuda_runtime.h>
#include <math.h>

#define S_LEN   2048
#define BATCH   64
#define ISZ     512
#define HSZ     512
#define G3      1536
#define NLAYERS 2

// ---------------- device scratch (no cudaMalloc allowed) ----------------
__device__ float g_xlin[(size_t)S_LEN * BATCH * G3];   // per-layer input projections
__device__ float g_y1[(size_t)S_LEN * BATCH * HSZ];    // layer-0 outputs
__device__ float g_hbuf[2][BATCH * HSZ];               // ping-pong hidden state
__device__ unsigned int g_bar;                         // grid barrier counter

// ---------------- packed f32x2 helpers (Blackwell FFMA2) ----------------
typedef unsigned long long u64;

__device__ __forceinline__ u64 pk2(float lo, float hi) {
    u64 r; asm("mov.b64 %0, {%1, %2};" : "=l"(r) : "f"(lo), "f"(hi)); return r;
}
__device__ __forceinline__ void fma2(u64& d, u64 a, u64 b) {
    asm("fma.rn.f32x2 %0, %1, %2, %3;" : "=l"(d) : "l"(a), "l"(b), "l"(d));
}
__device__ __forceinline__ float2 upk2(u64 v) {
    float2 r; asm("mov.b64 {%0, %1}, %2;" : "=f"(r.x), "=f"(r.y) : "l"(v)); return r;
}

// =====================================================================
// GEMM: C[M,N] = A[M,K=512] * W[N,K=512]^T + bias[N]
// M = S*B = 131072, N = 1536. 128x128x8 tile, 8x8 per thread, FFMA2 core.
// =====================================================================
#define BM 128
#define BN 128
#define BK 8
#define TM 8
#define TN 8

__global__ __launch_bounds__(256) void gemm_xproj(
    const float* __restrict__ A, const float* __restrict__ W,
    const float* __restrict__ bias, float* __restrict__ C)
{
    __shared__ __align__(16) float As[BK][BM];
    __shared__ __align__(16) float Bs[BK][BN];

    const int bx = blockIdx.x;   // N tile
    const int by = blockIdx.y;   // M tile
    const int tid = threadIdx.x;
    const int tx = tid & 15;
    const int ty = tid >> 4;

    const float* Ab = A + (size_t)by * BM * ISZ;
    const float* Wb = W + (size_t)bx * BN * ISZ;

    const int lrow = tid >> 1;        // 0..127
    const int lcol = (tid & 1) * 4;   // 0 or 4

    u64 acc2[TM][TN / 2];
#pragma unroll
    for (int i = 0; i < TM; i++)
#pragma unroll
        for (int j = 0; j < TN / 2; j++) acc2[i][j] = 0ull;

    for (int k0 = 0; k0 < ISZ; k0 += BK) {
        float4 av = *(const float4*)(Ab + (size_t)lrow * ISZ + k0 + lcol);
        float4 wv = *(const float4*)(Wb + (size_t)lrow * ISZ + k0 + lcol);
        As[lcol + 0][lrow] = av.x; As[lcol + 1][lrow] = av.y;
        As[lcol + 2][lrow] = av.z; As[lcol + 3][lrow] = av.w;
        Bs[lcol + 0][lrow] = wv.x; Bs[lcol + 1][lrow] = wv.y;
        Bs[lcol + 2][lrow] = wv.z; Bs[lcol + 3][lrow] = wv.w;
        __syncthreads();

#pragma unroll
        for (int k = 0; k < BK; k++) {
            float4 a0 = *(const float4*)&As[k][ty * TM];
            float4 a1 = *(const float4*)&As[k][ty * TM + 4];
            // B pairs come out of smem already packed (consecutive floats)
            ulonglong2 b0 = *(const ulonglong2*)&Bs[k][tx * TN];
            ulonglong2 b1 = *(const ulonglong2*)&Bs[k][tx * TN + 4];
            const u64 bb[4] = {b0.x, b0.y, b1.x, b1.y};
            const float af[TM] = {a0.x, a0.y, a0.z, a0.w, a1.x, a1.y, a1.z, a1.w};
#pragma unroll
            for (int i = 0; i < TM; i++) {
                const u64 aa = pk2(af[i], af[i]);
#pragma unroll
                for (int j = 0; j < TN / 2; j++) fma2(acc2[i][j], aa, bb[j]);
            }
        }
        __syncthreads();
    }

    // epilogue: unpack, add bias, store
    const int n = bx * BN + tx * TN;
    float bsv[TN];
#pragma unroll
    for (int j = 0; j < TN; j++) bsv[j] = __ldg(&bias[n + j]);

#pragma unroll
    for (int i = 0; i < TM; i++) {
        const size_t m = (size_t)by * BM + ty * TM + i;
        float2 p0 = upk2(acc2[i][0]), p1 = upk2(acc2[i][1]);
        float2 p2 = upk2(acc2[i][2]), p3 = upk2(acc2[i][3]);
        float4 v0 = {p0.x + bsv[0], p0.y + bsv[1], p1.x + bsv[2], p1.y + bsv[3]};
        float4 v1 = {p2.x + bsv[4], p2.y + bsv[5], p3.x + bsv[6], p3.y + bsv[7]};
        *(float4*)(C + m * G3 + n)     = v0;
        *(float4*)(C + m * G3 + n + 4) = v1;
    }
}

// =====================================================================
// Recurrent GRU kernel: persistent, 128 blocks (32 h-chunks x 4 b-chunks),
// W_hh register-resident (packed f32x2), one grid barrier per timestep.
// =====================================================================
#define HC   16      // h indices per block
#define BC   16      // batches per block
#define NBLK ((HSZ / HC) * (BATCH / BC))   // 128
#define KSL  32      // K slice per thread
#define REDS 9       // padded warp-partial stride

// smem layout (floats)
#define SM_HS   0                     // h_s[BC][HSZ]         = 8192
#define SM_RED  (BC * HSZ)            // red[256][3][REDS]    = 6912
#define SM_XL   (SM_RED + 256 * 3 * REDS)   // xl_s[3][256]   = 768
#define SM_BH   (SM_XL + 768)         // bh_s[3][HC]          = 48
#define SM_TOT  (SM_BH + 48)
#define SMEM_BYTES (SM_TOT * 4)

__device__ __forceinline__ void grid_bar(unsigned* epoch)
{
    __syncthreads();
    if (threadIdx.x == 0) {
        __threadfence();
        atomicAdd(&g_bar, 1u);
        const unsigned target = (++(*epoch)) * gridDim.x;
        volatile unsigned* p = &g_bar;
        while (*p < target) { }
        __threadfence();
    }
    __syncthreads();
}

__global__ __launch_bounds__(256, 1) void gru_recurrent(
    const float* __restrict__ xlin,   // [S*B][G3]  (b_ih already added)
    const float* __restrict__ whh,    // [G3][HSZ]  this layer
    const float* __restrict__ bhh,    // [G3]       this layer
    const float* __restrict__ hx,     // [B*HSZ]    initial hidden
    float* __restrict__ yout,         // [S*B*HSZ]  layer outputs
    float* __restrict__ hfin)         // [B*HSZ]    final hidden
{
    extern __shared__ __align__(16) float sm[];
    float* h_s  = sm + SM_HS;
    float* red  = sm + SM_RED;
    float* xl_s = sm + SM_XL;
    float* bh_s = sm + SM_BH;

    const int blk = blockIdx.x;
    const int hc = blk >> 2;          // 0..31
    const int bc = blk & 3;           // 0..3
    const int hbase = hc * HC;
    const int bbase = bc * BC;
    const int tid  = threadIdx.x;
    const int j    = tid & 15;        // h index within chunk (matmul role)
    const int ks   = tid >> 4;        // k-slice 0..15
    const int lane = tid & 31;
    const int warp = tid >> 5;

    // ---- W_hh slice into registers, packed pairs: 3 gates x 16 f32x2 ----
    u64 wr2[KSL / 2], wz2[KSL / 2], wn2[KSL / 2];
    {
        const u64* rowr = (const u64*)(whh + (size_t)(0 * HSZ + hbase + j) * HSZ + ks * KSL);
        const u64* rowz = (const u64*)(whh + (size_t)(1 * HSZ + hbase + j) * HSZ + ks * KSL);
        const u64* rown = (const u64*)(whh + (size_t)(2 * HSZ + hbase + j) * HSZ + ks * KSL);
#pragma unroll
        for (int q = 0; q < KSL / 2; q++) {
            wr2[q] = rowr[q]; wz2[q] = rowz[q]; wn2[q] = rown[q];
        }
    }
    if (tid < HC) {
        bh_s[tid]          = bhh[0 * HSZ + hbase + tid];
        bh_s[HC + tid]     = bhh[1 * HSZ + hbase + tid];
        bh_s[2 * HC + tid] = bhh[2 * HSZ + hbase + tid];
    }

    // ---- init hidden state (buffer 0) for this block's tile ----
    {
        const int jj = tid >> 4, bb = tid & 15;
        const size_t idx = (size_t)(bbase + bb) * HSZ + hbase + jj;
        g_hbuf[0][idx] = hx[idx];
    }
    unsigned epoch = 0;
    grid_bar(&epoch);

    for (int t = 0; t < S_LEN; t++) {
        // ---- stage h (our 16 batches, full H) and this step's xlin ----
        {
            const float4* src = (const float4*)(g_hbuf[t & 1] + (size_t)bbase * HSZ);
            float4* dst = (float4*)h_s;
#pragma unroll
            for (int r = 0; r < 8; r++)
                dst[tid + 256 * r] = __ldcg(src + tid + 256 * r);

            const int bb = tid >> 4, jj = tid & 15;
            const float* xp = xlin + ((size_t)t * BATCH + bbase + bb) * G3 + hbase + jj;
#pragma unroll
            for (int g = 0; g < 3; g++)
                xl_s[g * 256 + tid] = __ldg(xp + g * HSZ);
        }
        __syncthreads();

        // ---- matmul partials: thread (j, ks): 3 gates over its k-slice, FFMA2 ----
#pragma unroll 2
        for (int b = 0; b < BC; b++) {
            u64 ar2 = 0ull, az2 = 0ull, an2 = 0ull;
            const ulonglong2* hp = (const ulonglong2*)(h_s + b * HSZ + ks * KSL);
#pragma unroll
            for (int q = 0; q < KSL / 4; q++) {
                ulonglong2 hv = hp[q];   // two packed h pairs
                fma2(ar2, wr2[2*q],     hv.x);
                fma2(az2, wz2[2*q],     hv.x);
                fma2(an2, wn2[2*q],     hv.x);
                fma2(ar2, wr2[2*q + 1], hv.y);
                fma2(az2, wz2[2*q + 1], hv.y);
                fma2(an2, wn2[2*q + 1], hv.y);
            }
            float2 arf = upk2(ar2), azf = upk2(az2), anf = upk2(an2);
            float ar = arf.x + arf.y;
            float az = azf.x + azf.y;
            float an = anf.x + anf.y;
            // fold k-slice pairs within the warp (ks and ks^1 in same warp)
            ar += __shfl_xor_sync(0xffffffffu, ar, 16);
            az += __shfl_xor_sync(0xffffffffu, az, 16);
            an += __shfl_xor_sync(0xffffffffu, an, 16);
            if (lane < 16) {
                float* rb = red + ((b * HC + j) * 3) * REDS + warp;
                rb[0]        = ar;
                rb[REDS]     = az;
                rb[2 * REDS] = an;
            }
        }
        __syncthreads();

        // ---- reduce 8 warp-partials, apply gates, update h ----
        {
            const int jj = tid & 15;   // h index (contiguous stores)
            const int bb = tid >> 4;   // batch
            const float* rb = red + ((bb * HC + jj) * 3) * REDS;
            float hr = 0.f, hz = 0.f, hn = 0.f;
#pragma unroll
            for (int w = 0; w < 8; w++) {
                hr += rb[w]; hz += rb[REDS + w]; hn += rb[2 * REDS + w];
            }
            hr += bh_s[jj]; hz += bh_s[HC + jj]; hn += bh_s[2 * HC + jj];

            const float xr = xl_s[0 * 256 + tid];
            const float xz = xl_s[1 * 256 + tid];
            const float xn = xl_s[2 * 256 + tid];

            const float r = 1.f / (1.f + __expf(-(xr + hr)));
            const float z = 1.f / (1.f + __expf(-(xz + hz)));
            const float n = tanhf(xn + r * hn);

            const int bg = bbase + bb;
            const int hg = hbase + jj;
            const float hold = h_s[bb * HSZ + hg];
            const float hnew = (1.f - z) * n + z * hold;

            g_hbuf[(t + 1) & 1][(size_t)bg * HSZ + hg] = hnew;
            yout[((size_t)t * BATCH + bg) * HSZ + hg] = hnew;
            if (t == S_LEN - 1) hfin[(size_t)bg * HSZ + hg] = hnew;
        }
        grid_bar(&epoch);
    }
}

// =====================================================================
// kernel_launch
// =====================================================================
extern "C" void kernel_launch(void* const* d_in, const int* in_sizes, int n_in,
                              void* d_out, int out_size)
{
    (void)in_sizes; (void)n_in; (void)out_size;
    const float* x   = (const float*)d_in[0];
    const float* hx  = (const float*)d_in[1];
    const float* wih = (const float*)d_in[2];
    const float* whh = (const float*)d_in[3];
    const float* bih = (const float*)d_in[4];
    const float* bhh = (const float*)d_in[5];

    float* out    = (float*)d_out;                            // [S,B,H]
    float* hidden = out + (size_t)S_LEN * BATCH * HSZ;        // [L,B,H]

    float* xlin = nullptr; float* y1 = nullptr; unsigned* bar = nullptr;
    cudaGetSymbolAddress((void**)&xlin, g_xlin);
    cudaGetSymbolAddress((void**)&y1,   g_y1);
    cudaGetSymbolAddress((void**)&bar,  g_bar);

    cudaFuncSetAttribute(gru_recurrent,
                         cudaFuncAttributeMaxDynamicSharedMemorySize, SMEM_BYTES);

    const dim3 gemm_grid(G3 / BN, (S_LEN * BATCH) / BM);

    // ---- layer 0 ----
    gemm_xproj<<<gemm_grid, 256>>>(x, wih, bih, xlin);
    cudaMemsetAsync(bar, 0, sizeof(unsigned));
    gru_recurrent<<<NBLK, 256, SMEM_BYTES>>>(xlin, whh, bhh, hx, y1, hidden);

    // ---- layer 1 ----
    gemm_xproj<<<gemm_grid, 256>>>(y1, wih + (size_t)G3 * ISZ, bih + G3, xlin);
    cudaMemsetAsync(bar, 0, sizeof(unsigned));
    gru_recurrent<<<NBLK, 256, SMEM_BYTES>>>(xlin, whh + (size_t)G3 * HSZ, bhh + G3,
                                             hx + (size_t)BATCH * HSZ,
                                             out, hidden + (size_t)BATCH * HSZ);
}

// round 4
// speedup vs baseline: 1.3629x; 1.3132x over previous
#include <cuda_runtime.h>
#include <math.h>

#define S_LEN   2048
#define BATCH   64
#define ISZ     512
#define HSZ     512
#define G3      1536
#define NLAYERS 2

// ---------------- device scratch (no cudaMalloc allowed) ----------------
__device__ float g_xlin[(size_t)S_LEN * BATCH * G3];   // per-layer input projections
__device__ float g_y1[(size_t)S_LEN * BATCH * HSZ];    // layer-0 outputs
__device__ float g_hbuf[2][BATCH * HSZ];               // ping-pong hidden state
__device__ unsigned int g_bar;                         // grid barrier counter

// ---------------- packed f32x2 helpers ----------------
typedef unsigned long long u64;

__device__ __forceinline__ u64 pk2(float lo, float hi) {
    u64 r; asm("mov.b64 %0, {%1, %2};" : "=l"(r) : "f"(lo), "f"(hi)); return r;
}
__device__ __forceinline__ void fma2(u64& d, u64 a, u64 b) {
    asm("fma.rn.f32x2 %0, %1, %2, %3;" : "=l"(d) : "l"(a), "l"(b), "l"(d));
}
__device__ __forceinline__ float2 upk2(u64 v) {
    float2 r; asm("mov.b64 {%0, %1}, %2;" : "=f"(r.x), "=f"(r.y) : "l"(v)); return r;
}

// ---------------- tf32 helpers ----------------
__device__ __forceinline__ float to_tf32(float x) {
    float r; asm("cvt.rna.tf32.f32 %0, %1;" : "=f"(r) : "f"(x)); return r;
}
__device__ __forceinline__ void mma_tf32(float* d, const unsigned* a, const unsigned* b) {
    asm("mma.sync.aligned.m16n8k8.row.col.f32.tf32.tf32.f32 "
        "{%0,%1,%2,%3}, {%4,%5,%6,%7}, {%8,%9}, {%0,%1,%2,%3};"
        : "+f"(d[0]), "+f"(d[1]), "+f"(d[2]), "+f"(d[3])
        : "r"(a[0]), "r"(a[1]), "r"(a[2]), "r"(a[3]), "r"(b[0]), "r"(b[1]));
}

// =====================================================================
// tf32 tensor-core GEMM: C[M,N] = A[M,K=512] * W[N,K=512]^T + bias[N]
// Block 128x128, 8 warps (2x4), warp tile 64x32, K staged 16, double buffer.
// =====================================================================
#define GBM 128
#define GBN 128
#define GBK 16
#define GSTAGES (ISZ / GBK)   // 32
#define APAD 20               // padded row stride (floats); conflict-free frags

__global__ __launch_bounds__(256) void gemm_xproj_tf32(
    const float* __restrict__ A, const float* __restrict__ W,
    const float* __restrict__ bias, float* __restrict__ C)
{
    __shared__ __align__(16) float As[2][GBM * APAD];
    __shared__ __align__(16) float Bs[2][GBN * APAD];

    const int bx = blockIdx.x;       // N tile (0..11)
    const int by = blockIdx.y;       // M tile (0..1023)
    const int tid  = threadIdx.x;
    const int lane = tid & 31;
    const int wid  = tid >> 5;
    const int wm = wid & 1;          // warp row (0..1)  -> 64 rows
    const int wn = wid >> 1;         // warp col (0..3)  -> 32 cols
    const int g  = lane >> 2;        // group id (0..7)
    const int t4 = lane & 3;         // thread in group

    // gmem staging indices: thread loads rows lrow and lrow+64, 16B each
    const int lrow = tid >> 2;           // 0..63
    const int lc4  = (tid & 3) * 4;      // col within 16-float stage

    const float* Ab = A + ((size_t)by * GBM + lrow) * ISZ + lc4;
    const float* Wb = W + ((size_t)bx * GBN + lrow) * ISZ + lc4;

    float4 av[2], wv[2];

    // prologue: stage 0
    av[0] = *(const float4*)(Ab);
    av[1] = *(const float4*)(Ab + (size_t)64 * ISZ);
    wv[0] = *(const float4*)(Wb);
    wv[1] = *(const float4*)(Wb + (size_t)64 * ISZ);
    {
        float* as0 = &As[0][lrow * APAD + lc4];
        float* bs0 = &Bs[0][lrow * APAD + lc4];
        as0[0] = to_tf32(av[0].x); as0[1] = to_tf32(av[0].y);
        as0[2] = to_tf32(av[0].z); as0[3] = to_tf32(av[0].w);
        as0[64 * APAD + 0] = to_tf32(av[1].x); as0[64 * APAD + 1] = to_tf32(av[1].y);
        as0[64 * APAD + 2] = to_tf32(av[1].z); as0[64 * APAD + 3] = to_tf32(av[1].w);
        bs0[0] = to_tf32(wv[0].x); bs0[1] = to_tf32(wv[0].y);
        bs0[2] = to_tf32(wv[0].z); bs0[3] = to_tf32(wv[0].w);
        bs0[64 * APAD + 0] = to_tf32(wv[1].x); bs0[64 * APAD + 1] = to_tf32(wv[1].y);
        bs0[64 * APAD + 2] = to_tf32(wv[1].z); bs0[64 * APAD + 3] = to_tf32(wv[1].w);
    }
    __syncthreads();

    float acc[4][4][4];
#pragma unroll
    for (int i = 0; i < 4; i++)
#pragma unroll
        for (int j = 0; j < 4; j++)
#pragma unroll
            for (int r = 0; r < 4; r++) acc[i][j][r] = 0.f;

    for (int s = 0; s < GSTAGES; s++) {
        const int cur = s & 1;
        if (s + 1 < GSTAGES) {
            const size_t ko = (size_t)(s + 1) * GBK;
            av[0] = *(const float4*)(Ab + ko);
            av[1] = *(const float4*)(Ab + (size_t)64 * ISZ + ko);
            wv[0] = *(const float4*)(Wb + ko);
            wv[1] = *(const float4*)(Wb + (size_t)64 * ISZ + ko);
        }

        const float* as = As[cur];
        const float* bs = Bs[cur];
#pragma unroll
        for (int kk = 0; kk < 2; kk++) {
            const int kb = kk * 8 + t4;
            unsigned af[4][4];
#pragma unroll
            for (int ms = 0; ms < 4; ms++) {
                const int r0 = (wm * 64 + ms * 16 + g) * APAD;
                af[ms][0] = __float_as_uint(as[r0 + kb]);
                af[ms][1] = __float_as_uint(as[r0 + 8 * APAD + kb]);
                af[ms][2] = __float_as_uint(as[r0 + kb + 4]);
                af[ms][3] = __float_as_uint(as[r0 + 8 * APAD + kb + 4]);
            }
#pragma unroll
            for (int ns = 0; ns < 4; ns++) {
                const int c0 = (wn * 32 + ns * 8 + g) * APAD;
                unsigned bf[2];
                bf[0] = __float_as_uint(bs[c0 + kb]);
                bf[1] = __float_as_uint(bs[c0 + kb + 4]);
#pragma unroll
                for (int ms = 0; ms < 4; ms++)
                    mma_tf32(acc[ms][ns], af[ms], bf);
            }
        }

        if (s + 1 < GSTAGES) {
            float* as1 = &As[cur ^ 1][lrow * APAD + lc4];
            float* bs1 = &Bs[cur ^ 1][lrow * APAD + lc4];
            as1[0] = to_tf32(av[0].x); as1[1] = to_tf32(av[0].y);
            as1[2] = to_tf32(av[0].z); as1[3] = to_tf32(av[0].w);
            as1[64 * APAD + 0] = to_tf32(av[1].x); as1[64 * APAD + 1] = to_tf32(av[1].y);
            as1[64 * APAD + 2] = to_tf32(av[1].z); as1[64 * APAD + 3] = to_tf32(av[1].w);
            bs1[0] = to_tf32(wv[0].x); bs1[1] = to_tf32(wv[0].y);
            bs1[2] = to_tf32(wv[0].z); bs1[3] = to_tf32(wv[0].w);
            bs1[64 * APAD + 0] = to_tf32(wv[1].x); bs1[64 * APAD + 1] = to_tf32(wv[1].y);
            bs1[64 * APAD + 2] = to_tf32(wv[1].z); bs1[64 * APAD + 3] = to_tf32(wv[1].w);
        }
        __syncthreads();
    }

    // epilogue: bias + store (float2 per fragment row)
    float bv[4][2];
#pragma unroll
    for (int ns = 0; ns < 4; ns++) {
        const int cn = bx * GBN + wn * 32 + ns * 8 + t4 * 2;
        bv[ns][0] = __ldg(&bias[cn]);
        bv[ns][1] = __ldg(&bias[cn + 1]);
    }
#pragma unroll
    for (int ms = 0; ms < 4; ms++) {
        const size_t r0 = (size_t)by * GBM + wm * 64 + ms * 16 + g;
#pragma unroll
        for (int ns = 0; ns < 4; ns++) {
            const int cn = bx * GBN + wn * 32 + ns * 8 + t4 * 2;
            float2 v0 = {acc[ms][ns][0] + bv[ns][0], acc[ms][ns][1] + bv[ns][1]};
            float2 v1 = {acc[ms][ns][2] + bv[ns][0], acc[ms][ns][3] + bv[ns][1]};
            *(float2*)(C + r0 * G3 + cn)       = v0;
            *(float2*)(C + (r0 + 8) * G3 + cn) = v1;
        }
    }
}

// =====================================================================
// Recurrent GRU kernel: persistent, 128 blocks (32 h-chunks x 4 b-chunks),
// W_hh register-resident (packed f32x2), grid barrier per timestep,
// x_lin prefetched one step ahead.
// =====================================================================
#define HC   16
#define BC   16
#define NBLK ((HSZ / HC) * (BATCH / BC))   // 128
#define KSL  32
#define REDS 9

#define SM_HS   0                     // h_s[BC][HSZ]         = 8192
#define SM_RED  (BC * HSZ)            // red[256][3][REDS]    = 6912
#define SM_XL   (SM_RED + 256 * 3 * REDS)   // xl_s[3][256]   = 768
#define SM_BH   (SM_XL + 768)         // bh_s[3][HC]          = 48
#define SM_TOT  (SM_BH + 48)
#define SMEM_BYTES (SM_TOT * 4)

__device__ __forceinline__ void grid_bar(unsigned* epoch)
{
    __syncthreads();
    if (threadIdx.x == 0) {
        __threadfence();
        atomicAdd(&g_bar, 1u);
        const unsigned target = (++(*epoch)) * gridDim.x;
        volatile unsigned* p = &g_bar;
        while (*p < target) { }
        __threadfence();
    }
    __syncthreads();
}

__global__ __launch_bounds__(256, 1) void gru_recurrent(
    const float* __restrict__ xlin,
    const float* __restrict__ whh,
    const float* __restrict__ bhh,
    const float* __restrict__ hx,
    float* __restrict__ yout,
    float* __restrict__ hfin)
{
    extern __shared__ __align__(16) float sm[];
    float* h_s  = sm + SM_HS;
    float* red  = sm + SM_RED;
    float* xl_s = sm + SM_XL;
    float* bh_s = sm + SM_BH;

    const int blk = blockIdx.x;
    const int hc = blk >> 2;
    const int bc = blk & 3;
    const int hbase = hc * HC;
    const int bbase = bc * BC;
    const int tid  = threadIdx.x;
    const int j    = tid & 15;
    const int ks   = tid >> 4;
    const int lane = tid & 31;
    const int warp = tid >> 5;

    // W_hh slice into registers, packed pairs
    u64 wr2[KSL / 2], wz2[KSL / 2], wn2[KSL / 2];
    {
        const u64* rowr = (const u64*)(whh + (size_t)(0 * HSZ + hbase + j) * HSZ + ks * KSL);
        const u64* rowz = (const u64*)(whh + (size_t)(1 * HSZ + hbase + j) * HSZ + ks * KSL);
        const u64* rown = (const u64*)(whh + (size_t)(2 * HSZ + hbase + j) * HSZ + ks * KSL);
#pragma unroll
        for (int q = 0; q < KSL / 2; q++) {
            wr2[q] = rowr[q]; wz2[q] = rowz[q]; wn2[q] = rown[q];
        }
    }
    if (tid < HC) {
        bh_s[tid]          = bhh[0 * HSZ + hbase + tid];
        bh_s[HC + tid]     = bhh[1 * HSZ + hbase + tid];
        bh_s[2 * HC + tid] = bhh[2 * HSZ + hbase + tid];
    }

    // init hidden state (buffer 0)
    {
        const int jj = tid >> 4, bb = tid & 15;
        const size_t idx = (size_t)(bbase + bb) * HSZ + hbase + jj;
        g_hbuf[0][idx] = hx[idx];
    }
    unsigned epoch = 0;
    grid_bar(&epoch);

    // prefetch x_lin for t=0
    const int pbb = tid >> 4, pjj = tid & 15;
    const float* xpbase = xlin + ((size_t)(bbase + pbb)) * G3 + hbase + pjj;
    float xn[3];
#pragma unroll
    for (int gk = 0; gk < 3; gk++) xn[gk] = __ldg(xpbase + gk * HSZ);

    for (int t = 0; t < S_LEN; t++) {
        // commit prefetched x_lin; stage h
        {
#pragma unroll
            for (int gk = 0; gk < 3; gk++) xl_s[gk * 256 + tid] = xn[gk];

            const float4* src = (const float4*)(g_hbuf[t & 1] + (size_t)bbase * HSZ);
            float4* dst = (float4*)h_s;
#pragma unroll
            for (int r = 0; r < 8; r++)
                dst[tid + 256 * r] = __ldcg(src + tid + 256 * r);
        }
        __syncthreads();

        // matmul partials (FFMA2 over register W_hh)
#pragma unroll 2
        for (int b = 0; b < BC; b++) {
            u64 ar2 = 0ull, az2 = 0ull, an2 = 0ull;
            const ulonglong2* hp = (const ulonglong2*)(h_s + b * HSZ + ks * KSL);
#pragma unroll
            for (int q = 0; q < KSL / 4; q++) {
                ulonglong2 hv = hp[q];
                fma2(ar2, wr2[2*q],     hv.x);
                fma2(az2, wz2[2*q],     hv.x);
                fma2(an2, wn2[2*q],     hv.x);
                fma2(ar2, wr2[2*q + 1], hv.y);
                fma2(az2, wz2[2*q + 1], hv.y);
                fma2(an2, wn2[2*q + 1], hv.y);
            }
            float2 arf = upk2(ar2), azf = upk2(az2), anf = upk2(an2);
            float ar = arf.x + arf.y;
            float az = azf.x + azf.y;
            float an = anf.x + anf.y;
            ar += __shfl_xor_sync(0xffffffffu, ar, 16);
            az += __shfl_xor_sync(0xffffffffu, az, 16);
            an += __shfl_xor_sync(0xffffffffu, an, 16);
            if (lane < 16) {
                float* rb = red + ((b * HC + j) * 3) * REDS + warp;
                rb[0]        = ar;
                rb[REDS]     = az;
                rb[2 * REDS] = an;
            }
        }

        // prefetch x_lin for t+1 (overlaps reduction + barrier)
        if (t + 1 < S_LEN) {
            const float* xp = xpbase + (size_t)(t + 1) * BATCH * G3;
#pragma unroll
            for (int gk = 0; gk < 3; gk++) xn[gk] = __ldg(xp + gk * HSZ);
        }
        __syncthreads();

        // reduce, gates, update
        {
            const int jj = tid & 15;
            const int bb = tid >> 4;
            const float* rb = red + ((bb * HC + jj) * 3) * REDS;
            float hr = 0.f, hz = 0.f, hn = 0.f;
#pragma unroll
            for (int w = 0; w < 8; w++) {
                hr += rb[w]; hz += rb[REDS + w]; hn += rb[2 * REDS + w];
            }
            hr += bh_s[jj]; hz += bh_s[HC + jj]; hn += bh_s[2 * HC + jj];

            const float xr = xl_s[0 * 256 + tid];
            const float xz = xl_s[1 * 256 + tid];
            const float xnn = xl_s[2 * 256 + tid];

            const float r = 1.f / (1.f + __expf(-(xr + hr)));
            const float z = 1.f / (1.f + __expf(-(xz + hz)));
            const float n = tanhf(xnn + r * hn);

            const int bg = bbase + bb;
            const int hg = hbase + jj;
            const float hold = h_s[bb * HSZ + hg];
            const float hnew = (1.f - z) * n + z * hold;

            g_hbuf[(t + 1) & 1][(size_t)bg * HSZ + hg] = hnew;
            yout[((size_t)t * BATCH + bg) * HSZ + hg] = hnew;
            if (t == S_LEN - 1) hfin[(size_t)bg * HSZ + hg] = hnew;
        }
        grid_bar(&epoch);
    }
}

// =====================================================================
// kernel_launch
// =====================================================================
extern "C" void kernel_launch(void* const* d_in, const int* in_sizes, int n_in,
                              void* d_out, int out_size)
{
    (void)in_sizes; (void)n_in; (void)out_size;
    const float* x   = (const float*)d_in[0];
    const float* hx  = (const float*)d_in[1];
    const float* wih = (const float*)d_in[2];
    const float* whh = (const float*)d_in[3];
    const float* bih = (const float*)d_in[4];
    const float* bhh = (const float*)d_in[5];

    float* out    = (float*)d_out;                            // [S,B,H]
    float* hidden = out + (size_t)S_LEN * BATCH * HSZ;        // [L,B,H]

    float* xlin = nullptr; float* y1 = nullptr; unsigned* bar = nullptr;
    cudaGetSymbolAddress((void**)&xlin, g_xlin);
    cudaGetSymbolAddress((void**)&y1,   g_y1);
    cudaGetSymbolAddress((void**)&bar,  g_bar);

    cudaFuncSetAttribute(gru_recurrent,
                         cudaFuncAttributeMaxDynamicSharedMemorySize, SMEM_BYTES);

    const dim3 gemm_grid(G3 / GBN, (S_LEN * BATCH) / GBM);

    // ---- layer 0 ----
    gemm_xproj_tf32<<<gemm_grid, 256>>>(x, wih, bih, xlin);
    cudaMemsetAsync(bar, 0, sizeof(unsigned));
    gru_recurrent<<<NBLK, 256, SMEM_BYTES>>>(xlin, whh, bhh, hx, y1, hidden);

    // ---- layer 1 ----
    gemm_xproj_tf32<<<gemm_grid, 256>>>(y1, wih + (size_t)G3 * ISZ, bih + G3, xlin);
    cudaMemsetAsync(bar, 0, sizeof(unsigned));
    gru_recurrent<<<NBLK, 256, SMEM_BYTES>>>(xlin, whh + (size_t)G3 * HSZ, bhh + G3,
                                             hx + (size_t)BATCH * HSZ,
                                             out, hidden + (size_t)BATCH * HSZ);
}